// round 2
// baseline (speedup 1.0000x reference)
#include <cuda_runtime.h>
#include <cuda_fp16.h>
#include <cuda_bf16.h>
#include <mma.h>
#include <math.h>
#include <stdint.h>

using namespace nvcuda;

#define CB 2
#define CT 1024
#define CD 256
#define CH 4
#define CNH 8192
#define CN 32768
#define CV 256
#define CL 6
#define FH 4096
#define EPSV 1e-5f
#define SLD 40

// ---------------- device scratch (no allocations allowed) ----------------
__device__ __align__(256) float  g_v   [CB*CT*CD];
__device__ __align__(256) __half g_vh  [CB*CT*CD];
__device__ __align__(256) __half g_vl  [CB*CT*CD];
__device__ __align__(256) float  g_x   [(size_t)CB*CH*CT*CNH];
__device__ __align__(256) __half g_qh  [(size_t)CB*CH*CT*CNH];
__device__ __align__(256) __half g_ql  [(size_t)CB*CH*CT*CNH];
__device__ __align__(256) __half g_sh  [(size_t)CB*CH*CT*CT];
__device__ __align__(256) __half g_sl  [(size_t)CB*CH*CT*CT];
__device__ __align__(256) float  g_a   [CB*CH*CT*CD];
__device__ __align__(256) __half g_lah [CB*CH*CT*CD];
__device__ __align__(256) __half g_lal [CB*CH*CT*CD];
__device__ __align__(256) __half g_yh  [(size_t)CB*CT*CN];
__device__ __align__(256) __half g_yl  [(size_t)CB*CT*CN];
__device__ __align__(256) float  g_zp  [(size_t)8*CB*CT*CD];
__device__ __align__(256) float  g_cosT[(size_t)CT*FH];
__device__ __align__(256) float  g_sinT[(size_t)CT*FH];
__device__ __align__(256) __half g_wxh [(size_t)CH*CD*CNH];
__device__ __align__(256) __half g_wxl [(size_t)CH*CD*CNH];
__device__ __align__(256) __half g_wyh [(size_t)CH*CD*CNH];
__device__ __align__(256) __half g_wyl [(size_t)CH*CD*CNH];
__device__ __align__(256) __half g_ench[(size_t)CN*CD];
__device__ __align__(256) __half g_encl[(size_t)CN*CD];
__device__ __align__(256) __half g_roh [CD*CV];
__device__ __align__(256) __half g_rol [CD*CV];

// ---------------- helpers ----------------
__device__ __forceinline__ float blkSum(float v, float* red){
    int lane = threadIdx.x & 31, w = threadIdx.x >> 5;
#pragma unroll
    for (int o = 16; o > 0; o >>= 1) v += __shfl_xor_sync(0xffffffffu, v, o);
    if (lane == 0) red[w] = v;
    __syncthreads();
    float r = 0.f;
#pragma unroll
    for (int i = 0; i < 8; i++) r += red[i];
    __syncthreads();
    return r;
}

__device__ __forceinline__ void split_store(__half* hi, __half* lo, size_t o, float v){
    __half h = __float2half(v);
    hi[o] = h;
    lo[o] = __float2half(v - __half2float(h));
}

// ---------------- small kernels ----------------
__global__ void k_tables(){
    int t = blockIdx.x;
    for (int i = threadIdx.x; i < FH; i += blockDim.x){
        double ex  = (2.0 * (double)i) / (double)CNH;
        double inv = exp(-ex * 9.210340371976184);  // 10000^-ex
        double ang = (double)t * inv;
        g_cosT[(size_t)t*FH + i] = (float)cos(ang);
        g_sinT[(size_t)t*FH + i] = (float)sin(ang);
    }
}

__global__ void k_split(const float* __restrict__ src, int sel, int n){
    __half *hi, *lo;
    if      (sel == 0){ hi = g_wxh;  lo = g_wxl;  }
    else if (sel == 1){ hi = g_wyh;  lo = g_wyl;  }
    else if (sel == 2){ hi = g_ench; lo = g_encl; }
    else              { hi = g_roh;  lo = g_rol;  }
    for (int i = blockIdx.x*blockDim.x + threadIdx.x; i < n; i += gridDim.x*blockDim.x){
        float v = src[i];
        __half h = __float2half(v);
        hi[i] = h;
        lo[i] = __float2half(v - __half2float(h));
    }
}

__global__ void k_init_v(const int* __restrict__ idx, const float* __restrict__ wte){
    __shared__ float red[8];
    int bt = blockIdx.x, d = threadIdx.x;
    float x = wte[(size_t)idx[bt]*CD + d];
    float m = blkSum(x, red) * (1.f/CD);
    float c = x - m;
    float var = blkSum(c*c, red) * (1.f/CD);
    float o = c * rsqrtf(var + EPSV);
    size_t oi = (size_t)bt*CD + d;
    g_v[oi] = o;
    split_store(g_vh, g_vl, oi, o);
}

__global__ void k_lna(){
    __shared__ float red[8];
    int row = blockIdx.x, d = threadIdx.x;
    float x = g_a[(size_t)row*CD + d];
    float m = blkSum(x, red) * (1.f/CD);
    float c = x - m;
    float var = blkSum(c*c, red) * (1.f/CD);
    float o = c * rsqrtf(var + EPSV);
    split_store(g_lah, g_lal, (size_t)row*CD + d, o);
}

__global__ void k_post(){
    __shared__ float red[8];
    int row = blockIdx.x, d = threadIdx.x;
    size_t oi = (size_t)row*CD + d;
    float z = 0.f;
#pragma unroll
    for (int p = 0; p < 8; p++) z += g_zp[(size_t)p*CB*CT*CD + oi];
    float m = blkSum(z, red) * (1.f/CD);
    float c = z - m;
    float var = blkSum(c*c, red) * (1.f/CD);
    float lnz = c * rsqrtf(var + EPSV);
    float u = g_v[oi] + lnz;
    m = blkSum(u, red) * (1.f/CD);
    c = u - m;
    var = blkSum(c*c, red) * (1.f/CD);
    float o = c * rsqrtf(var + EPSV);
    g_v[oi] = o;
    split_store(g_vh, g_vl, oi, o);
}

// ---------------- fused split-fp16 GEMM ----------------
#define M_XPROJ  0
#define M_SCORES 1
#define M_AMODE  2
#define M_YPROJ  3
#define M_ENC    4
#define M_RO     5

template<int MODE>
__global__ void __launch_bounds__(256) k_gemm(float* out_arg){
    __shared__ __align__(16) char smraw[40960];
    __half* sA_h = (__half*)(smraw);
    __half* sA_l = (__half*)(smraw + 10240);
    __half* sB_h = (__half*)(smraw + 20480);
    __half* sB_l = (__half*)(smraw + 30720);
    float*  sE   = (float*)(smraw);

    int tid  = threadIdx.x;
    int warp = tid >> 5;
    int wr   = warp >> 1, wc = warp & 1;

    int bh = blockIdx.z, b = bh >> 2, h = bh & 3;
    const __half *Ah, *Al, *Bh, *Bl;
    size_t lda, ldb;
    int m0, n0, Klen;

    if (MODE == M_XPROJ){
        Ah = g_vh + (size_t)b*CT*CD;   Al = g_vl + (size_t)b*CT*CD;   lda = CD;
        Bh = g_wxh + (size_t)h*CD*CNH; Bl = g_wxl + (size_t)h*CD*CNH; ldb = CNH;
        m0 = blockIdx.y*128; n0 = blockIdx.x*128; Klen = CD;
    } else if (MODE == M_YPROJ){
        Ah = g_lah + (size_t)bh*CT*CD; Al = g_lal + (size_t)bh*CT*CD; lda = CD;
        Bh = g_wyh + (size_t)h*CD*CNH; Bl = g_wyl + (size_t)h*CD*CNH; ldb = CNH;
        m0 = blockIdx.y*128; n0 = blockIdx.x*128; Klen = CD;
    } else if (MODE == M_SCORES){
        int p = blockIdx.x;
        int tT = 0, acc = 0;
        while (acc + tT + 1 <= p){ tT++; acc += tT; }
        int sT = p - acc;
        Ah = g_qh + (size_t)bh*CT*CNH; Al = g_ql + (size_t)bh*CT*CNH; lda = CNH;
        Bh = Ah; Bl = Al; ldb = CNH;
        m0 = tT*128; n0 = sT*128; Klen = CNH;
    } else if (MODE == M_AMODE){
        Ah = g_sh + (size_t)bh*CT*CT;  Al = g_sl + (size_t)bh*CT*CT;  lda = CT;
        Bh = g_vh + (size_t)b*CT*CD;   Bl = g_vl + (size_t)b*CT*CD;   ldb = CD;
        m0 = blockIdx.y*128; n0 = blockIdx.x*128;
        Klen = (blockIdx.y + 1) * 128;       // causal clamp: only s-tiles <= t-tile
    } else if (MODE == M_ENC){
        size_t k0 = (size_t)blockIdx.z * 4096;
        Ah = g_yh + k0; Al = g_yl + k0; lda = CN;
        Bh = g_ench + k0*CD; Bl = g_encl + k0*CD; ldb = CD;
        m0 = blockIdx.y*128; n0 = blockIdx.x*128; Klen = 4096;
    } else { // M_RO
        Ah = g_vh; Al = g_vl; lda = CD;
        Bh = g_roh; Bl = g_rol; ldb = CV;
        m0 = blockIdx.y*128; n0 = blockIdx.x*128; Klen = CD;
    }

    wmma::fragment<wmma::accumulator,16,16,16,float> facc[2][4];
#pragma unroll
    for (int i = 0; i < 2; i++)
#pragma unroll
        for (int j = 0; j < 4; j++) wmma::fill_fragment(facc[i][j], 0.f);

    for (int kb = 0; kb < Klen; kb += 32){
        // stage A: 128 rows x 32 halves (hi + lo)
        {
            int r = tid >> 1, ks = (tid & 1) << 4;
            const uint4* pah = (const uint4*)(Ah + (size_t)(m0 + r)*lda + kb + ks);
            const uint4* pal = (const uint4*)(Al + (size_t)(m0 + r)*lda + kb + ks);
            uint4* dh = (uint4*)&sA_h[r*SLD + ks];
            uint4* dl = (uint4*)&sA_l[r*SLD + ks];
            dh[0] = pah[0]; dh[1] = pah[1];
            dl[0] = pal[0]; dl[1] = pal[1];
        }
        // stage B (always n-major [n][k] in smem)
        if (MODE == M_SCORES){
            int r = tid >> 1, ks = (tid & 1) << 4;
            const uint4* pbh = (const uint4*)(Bh + (size_t)(n0 + r)*ldb + kb + ks);
            const uint4* pbl = (const uint4*)(Bl + (size_t)(n0 + r)*ldb + kb + ks);
            uint4* dh = (uint4*)&sB_h[r*SLD + ks];
            uint4* dl = (uint4*)&sB_l[r*SLD + ks];
            dh[0] = pbh[0]; dh[1] = pbh[1];
            dl[0] = pbl[0]; dl[1] = pbl[1];
        } else {
            int kk = tid >> 3, nn0 = (tid & 7) << 4;
            const __half* pbh = Bh + (size_t)(kb + kk)*ldb + n0 + nn0;
            const __half* pbl = Bl + (size_t)(kb + kk)*ldb + n0 + nn0;
            uint4 u0 = ((const uint4*)pbh)[0], u1 = ((const uint4*)pbh)[1];
            uint4 v0 = ((const uint4*)pbl)[0], v1 = ((const uint4*)pbl)[1];
            __half hb[16], lb[16];
            *(uint4*)&hb[0] = u0; *(uint4*)&hb[8] = u1;
            *(uint4*)&lb[0] = v0; *(uint4*)&lb[8] = v1;
#pragma unroll
            for (int j = 0; j < 16; j++){
                sB_h[(nn0 + j)*SLD + kk] = hb[j];
                sB_l[(nn0 + j)*SLD + kk] = lb[j];
            }
        }
        __syncthreads();

#pragma unroll
        for (int ks = 0; ks < 32; ks += 16){
            wmma::fragment<wmma::matrix_a,16,16,16,__half,wmma::row_major> fa_h[2], fa_l[2];
#pragma unroll
            for (int i = 0; i < 2; i++){
                wmma::load_matrix_sync(fa_h[i], &sA_h[(wr*32 + i*16)*SLD + ks], SLD);
                wmma::load_matrix_sync(fa_l[i], &sA_l[(wr*32 + i*16)*SLD + ks], SLD);
            }
#pragma unroll
            for (int j = 0; j < 4; j++){
                wmma::fragment<wmma::matrix_b,16,16,16,__half,wmma::col_major> fb_h, fb_l;
                wmma::load_matrix_sync(fb_h, &sB_h[(wc*64 + j*16)*SLD + ks], SLD);
                wmma::load_matrix_sync(fb_l, &sB_l[(wc*64 + j*16)*SLD + ks], SLD);
#pragma unroll
                for (int i = 0; i < 2; i++){
                    wmma::mma_sync(facc[i][j], fa_h[i], fb_h, facc[i][j]);
                    wmma::mma_sync(facc[i][j], fa_h[i], fb_l, facc[i][j]);
                    wmma::mma_sync(facc[i][j], fa_l[i], fb_h, facc[i][j]);
                }
            }
        }
        __syncthreads();
    }

    // ---------------- epilogue ----------------
    if (MODE == M_AMODE || MODE == M_ENC || MODE == M_RO){
        float* op; size_t ldo;
        if (MODE == M_AMODE){ op = g_a + (size_t)bh*CT*CD; ldo = CD; }
        else if (MODE == M_ENC){ op = g_zp + (size_t)blockIdx.z*CB*CT*CD; ldo = CD; }
        else { op = out_arg; ldo = CV; }
#pragma unroll
        for (int i = 0; i < 2; i++)
#pragma unroll
            for (int j = 0; j < 4; j++)
                wmma::store_matrix_sync(&op[(size_t)(m0 + wr*32 + i*16)*ldo + n0 + wc*64 + j*16],
                                        facc[i][j], ldo, wmma::mem_row_major);
        return;
    }

    // shared-routed epilogues (two 128x64 column chunks)
    for (int ch = 0; ch < 2; ch++){
        if (wc == ch){
#pragma unroll
            for (int i = 0; i < 2; i++)
#pragma unroll
                for (int j = 0; j < 4; j++)
                    wmma::store_matrix_sync(&sE[(wr*32 + i*16)*64 + j*16], facc[i][j], 64, wmma::mem_row_major);
        }
        __syncthreads();
        int nbase = n0 + ch*64;

        if (MODE == M_SCORES){
            size_t sbase = (size_t)bh*CT*CT;
#pragma unroll
            for (int e = 0; e < 32; e++){
                int idx = tid + e*256;
                int r = idx >> 6, c = idx & 63;
                int t = m0 + r, s = nbase + c;
                float v = sE[r*64 + c];
                if (s >= t) v = 0.f;               // strict causal: keep s < t
                split_store(g_sh, g_sl, sbase + (size_t)t*CT + s, v);
            }
        } else if (MODE == M_XPROJ){
            size_t xbase = (size_t)bh*CT*CNH;
#pragma unroll
            for (int e = 0; e < 16; e++){
                int idx = tid + e*256;
                int r = idx >> 5, pc = idx & 31;
                int t = m0 + r, n = nbase + pc*2;
                float x1 = fmaxf(sE[r*64 + pc*2    ], 0.f);
                float x2 = fmaxf(sE[r*64 + pc*2 + 1], 0.f);
                size_t xi = xbase + (size_t)t*CNH + n;
                g_x[xi] = x1; g_x[xi + 1] = x2;
                int fi = n >> 1;
                float cs = g_cosT[(size_t)t*FH + fi];
                float sn = g_sinT[(size_t)t*FH + fi];
                split_store(g_qh, g_ql, xi,     x1*cs - x2*sn);
                split_store(g_qh, g_ql, xi + 1, x1*sn + x2*cs);
            }
        } else { // M_YPROJ
            size_t xbase = (size_t)bh*CT*CNH;
#pragma unroll
            for (int e = 0; e < 32; e++){
                int idx = tid + e*256;
                int r = idx >> 6, c = idx & 63;
                int t = m0 + r, n = nbase + c;
                size_t xi = xbase + (size_t)t*CNH + n;
                float yv = fmaxf(sE[r*64 + c], 0.f) * g_x[xi];
                split_store(g_yh, g_yl, ((size_t)b*CT + t)*CN + (size_t)h*CNH + n, yv);
            }
        }
        __syncthreads();
    }
}

// ---------------- launch ----------------
extern "C" void kernel_launch(void* const* d_in, const int* in_sizes, int n_in,
                              void* d_out, int out_size){
    const int*   idx = (const int*)  d_in[0];
    const float* wte = (const float*)d_in[1];
    const float* enc = (const float*)d_in[2];
    const float* dx  = (const float*)d_in[3];
    const float* dy  = (const float*)d_in[4];
    const float* ro  = (const float*)d_in[5];
    float* out = (float*)d_out;

    k_tables<<<CT, 256>>>();
    k_split<<<2048, 256>>>(dx,  0, CH*CD*CNH);
    k_split<<<2048, 256>>>(dy,  1, CH*CD*CNH);
    k_split<<<2048, 256>>>(enc, 2, CN*CD);
    k_split<<<256,  256>>>(ro,  3, CD*CV);
    k_init_v<<<CB*CT, 256>>>(idx, wte);

    for (int l = 0; l < CL; l++){
        k_gemm<M_XPROJ> <<<dim3(CNH/128, CT/128, CB*CH), 256>>>(nullptr);
        k_gemm<M_SCORES><<<dim3(36,       1,      CB*CH), 256>>>(nullptr);
        k_gemm<M_AMODE> <<<dim3(CD/128,  CT/128, CB*CH), 256>>>(nullptr);
        k_lna<<<CB*CH*CT, 256>>>();
        k_gemm<M_YPROJ> <<<dim3(CNH/128, CT/128, CB*CH), 256>>>(nullptr);
        k_gemm<M_ENC>   <<<dim3(CD/128, (CB*CT)/128, 8), 256>>>(nullptr);
        k_post<<<CB*CT, 256>>>();
    }
    k_gemm<M_RO><<<dim3(CV/128, (CB*CT)/128, 1), 256>>>(out);
}

// round 4
// speedup vs baseline: 1.5453x; 1.5453x over previous
#include <cuda_runtime.h>
#include <cuda_fp16.h>
#include <math.h>
#include <stdint.h>

#define CB 2
#define CT 1024
#define CD 256
#define CH 4
#define CNH 8192
#define CN 32768
#define CV 256
#define CL 6
#define FH 4096
#define EPSV 1e-5f

// smem geometry: 4 arrays (Ah, Al, Bh, Bl), 128 rows x 128B data, 144B pitch
#define PITCH 144
#define ARR_BYTES (128*PITCH)          // 18432
#define STAGE_BYTES (4*ARR_BYTES)      // 73728
#define SMEM_BYTES (2*STAGE_BYTES)     // 147456

// ---------------- device scratch ----------------
__device__ __align__(256) float  g_v   [CB*CT*CD];
__device__ __align__(256) __half g_vh  [CB*CT*CD];
__device__ __align__(256) __half g_vl  [CB*CT*CD];
__device__ __align__(256) __half g_vTh [CB*CD*CT];
__device__ __align__(256) __half g_vTl [CB*CD*CT];
__device__ __align__(256) float  g_x   [(size_t)CB*CH*CT*CNH];
__device__ __align__(256) __half g_qh  [(size_t)CB*CH*CT*CNH];
__device__ __align__(256) __half g_ql  [(size_t)CB*CH*CT*CNH];
__device__ __align__(256) __half g_sh  [(size_t)CB*CH*CT*CT];
__device__ __align__(256) __half g_sl  [(size_t)CB*CH*CT*CT];
__device__ __align__(256) float  g_a   [CB*CH*CT*CD];
__device__ __align__(256) __half g_lah [CB*CH*CT*CD];
__device__ __align__(256) __half g_lal [CB*CH*CT*CD];
__device__ __align__(256) __half g_yh  [(size_t)CB*CT*CN];
__device__ __align__(256) __half g_yl  [(size_t)CB*CT*CN];
__device__ __align__(256) float  g_zp  [(size_t)8*CB*CT*CD];
__device__ __align__(256) float  g_cosT[(size_t)CT*FH];
__device__ __align__(256) float  g_sinT[(size_t)CT*FH];
// weights stored TRANSPOSED (K-major for B operand): [h][n][d] / [d][n] / [v][d]
__device__ __align__(256) __half g_wxh [(size_t)CH*CD*CNH];
__device__ __align__(256) __half g_wxl [(size_t)CH*CD*CNH];
__device__ __align__(256) __half g_wyh [(size_t)CH*CD*CNH];
__device__ __align__(256) __half g_wyl [(size_t)CH*CD*CNH];
__device__ __align__(256) __half g_ench[(size_t)CN*CD];
__device__ __align__(256) __half g_encl[(size_t)CN*CD];
__device__ __align__(256) __half g_roh [CD*CV];
__device__ __align__(256) __half g_rol [CD*CV];

// ---------------- PTX helpers ----------------
__device__ __forceinline__ uint32_t smem_u32(const void* p){
    uint32_t a;
    asm("{ .reg .u64 t; cvta.to.shared.u64 t, %1; cvt.u32.u64 %0, t; }" : "=r"(a) : "l"(p));
    return a;
}
__device__ __forceinline__ void cpa16(uint32_t s, const void* g){
    asm volatile("cp.async.cg.shared.global [%0], [%1], 16;" :: "r"(s), "l"(g));
}
__device__ __forceinline__ void ldm4(uint32_t* r, uint32_t a){
    asm volatile("ldmatrix.sync.aligned.m8n8.x4.shared.b16 {%0,%1,%2,%3}, [%4];"
        : "=r"(r[0]), "=r"(r[1]), "=r"(r[2]), "=r"(r[3]) : "r"(a));
}
__device__ __forceinline__ void mma16816(float* d, const uint32_t* a, const uint32_t* b){
    asm volatile(
        "mma.sync.aligned.m16n8k16.row.col.f32.f16.f16.f32 "
        "{%0,%1,%2,%3}, {%4,%5,%6,%7}, {%8,%9}, {%0,%1,%2,%3};"
        : "+f"(d[0]), "+f"(d[1]), "+f"(d[2]), "+f"(d[3])
        : "r"(a[0]), "r"(a[1]), "r"(a[2]), "r"(a[3]), "r"(b[0]), "r"(b[1]));
}

// ---------------- small helpers ----------------
__device__ __forceinline__ float blkSum(float v, float* red){
    int lane = threadIdx.x & 31, w = threadIdx.x >> 5;
#pragma unroll
    for (int o = 16; o > 0; o >>= 1) v += __shfl_xor_sync(0xffffffffu, v, o);
    if (lane == 0) red[w] = v;
    __syncthreads();
    float r = 0.f;
#pragma unroll
    for (int i = 0; i < 8; i++) r += red[i];
    __syncthreads();
    return r;
}
__device__ __forceinline__ void split_store(__half* hi, __half* lo, size_t o, float v){
    __half h = __float2half(v);
    hi[o] = h;
    lo[o] = __float2half(v - __half2float(h));
}
__device__ __forceinline__ void split_pack(float v0, float v1, uint32_t& hi, uint32_t& lo){
    __half h0 = __float2half(v0), h1 = __float2half(v1);
    hi = (uint32_t)__half_as_ushort(h0) | ((uint32_t)__half_as_ushort(h1) << 16);
    __half l0 = __float2half(v0 - __half2float(h0));
    __half l1 = __float2half(v1 - __half2float(h1));
    lo = (uint32_t)__half_as_ushort(l0) | ((uint32_t)__half_as_ushort(l1) << 16);
}

// ---------------- init kernels ----------------
__global__ void k_tables(){
    int i = blockIdx.x;                       // frequency index 0..FH-1
    double ex  = (2.0 * (double)i) / (double)CNH;
    double inv = exp(-ex * 9.210340371976184);
    for (int t = threadIdx.x; t < CT; t += blockDim.x){
        double ang = (double)t * inv;
        double k = rint(ang * 0.15915494309189535);
        float red = (float)(ang - k * 6.283185307179586);
        float s, c;
        sincosf(red, &s, &c);
        g_cosT[(size_t)t*FH + i] = c;
        g_sinT[(size_t)t*FH + i] = s;
    }
}

// transpose-split: in [h][R][C] fp32 -> out [h][C][R] hi/lo halves
__global__ void k_splitT(const float* __restrict__ src, int sel, int R, int C){
    __half *hi, *lo;
    if      (sel == 0){ hi = g_wxh;  lo = g_wxl;  }
    else if (sel == 1){ hi = g_wyh;  lo = g_wyl;  }
    else if (sel == 2){ hi = g_ench; lo = g_encl; }
    else              { hi = g_roh;  lo = g_rol;  }
    __shared__ float tile[32][33];
    int h = blockIdx.z;
    const float* s = src + (size_t)h*R*C;
    __half* oh = hi + (size_t)h*R*C;
    __half* ol = lo + (size_t)h*R*C;
    int c0 = blockIdx.x*32, r0 = blockIdx.y*32;
    for (int i = threadIdx.y; i < 32; i += 8)
        tile[i][threadIdx.x] = s[(size_t)(r0+i)*C + c0 + threadIdx.x];
    __syncthreads();
    for (int i = threadIdx.y; i < 32; i += 8){
        float v = tile[threadIdx.x][i];
        __half hh = __float2half(v);
        size_t o = (size_t)(c0+i)*R + r0 + threadIdx.x;
        oh[o] = hh;
        ol[o] = __float2half(v - __half2float(hh));
    }
}

__global__ void k_init_v(const int* __restrict__ idx, const float* __restrict__ wte){
    __shared__ float red[8];
    int bt = blockIdx.x, d = threadIdx.x;
    int b = bt >> 10, t = bt & 1023;
    float x = wte[(size_t)idx[bt]*CD + d];
    float m = blkSum(x, red) * (1.f/CD);
    float c = x - m;
    float var = blkSum(c*c, red) * (1.f/CD);
    float o = c * rsqrtf(var + EPSV);
    size_t oi = (size_t)bt*CD + d;
    g_v[oi] = o;
    split_store(g_vh, g_vl, oi, o);
    split_store(g_vTh, g_vTl, ((size_t)b*CD + d)*CT + t, o);
}

__global__ void k_lna(){
    __shared__ float red[8];
    int row = blockIdx.x, d = threadIdx.x;
    float x = g_a[(size_t)row*CD + d];
    float m = blkSum(x, red) * (1.f/CD);
    float c = x - m;
    float var = blkSum(c*c, red) * (1.f/CD);
    float o = c * rsqrtf(var + EPSV);
    split_store(g_lah, g_lal, (size_t)row*CD + d, o);
}

__global__ void k_post(){
    __shared__ float red[8];
    int row = blockIdx.x, d = threadIdx.x;
    int b = row >> 10, t = row & 1023;
    size_t oi = (size_t)row*CD + d;
    float z = 0.f;
#pragma unroll
    for (int p = 0; p < 8; p++) z += g_zp[(size_t)p*CB*CT*CD + oi];
    float m = blkSum(z, red) * (1.f/CD);
    float c = z - m;
    float var = blkSum(c*c, red) * (1.f/CD);
    float lnz = c * rsqrtf(var + EPSV);
    float u = g_v[oi] + lnz;
    m = blkSum(u, red) * (1.f/CD);
    c = u - m;
    var = blkSum(c*c, red) * (1.f/CD);
    float o = c * rsqrtf(var + EPSV);
    g_v[oi] = o;
    split_store(g_vh, g_vl, oi, o);
    split_store(g_vTh, g_vTl, ((size_t)b*CD + d)*CT + t, o);
}

// ---------------- unified split-fp16 mma.sync GEMM ----------------
#define M_XPROJ  0
#define M_SCORES 1
#define M_AMODE  2
#define M_YPROJ  3
#define M_ENC    4
#define M_RO     5

template<int MODE>
__global__ void __launch_bounds__(256) k_gemm(float* out_arg){
    extern __shared__ __align__(128) char dyn[];
    uint32_t smb = smem_u32(dyn);

    int tid  = threadIdx.x;
    int warp = tid >> 5, lane = tid & 31;
    int wr = warp >> 1, wc = warp & 1;          // warp tile: rows wr*32, cols wc*64

    int bh = blockIdx.z, b = bh >> 2, h = bh & 3;
    const __half *Ah, *Al, *Bh, *Bl;
    size_t lda, ldb;
    int m0, n0, Klen;

    if (MODE == M_XPROJ){
        Ah = g_vh + (size_t)b*CT*CD;   Al = g_vl + (size_t)b*CT*CD;   lda = CD;
        Bh = g_wxh + (size_t)h*CD*CNH; Bl = g_wxl + (size_t)h*CD*CNH; ldb = CD;
        m0 = blockIdx.y*128; n0 = blockIdx.x*128; Klen = CD;
    } else if (MODE == M_YPROJ){
        Ah = g_lah + (size_t)bh*CT*CD; Al = g_lal + (size_t)bh*CT*CD; lda = CD;
        Bh = g_wyh + (size_t)h*CD*CNH; Bl = g_wyl + (size_t)h*CD*CNH; ldb = CD;
        m0 = blockIdx.y*128; n0 = blockIdx.x*128; Klen = CD;
    } else if (MODE == M_SCORES){
        int p = blockIdx.x, tT = 0, acc0 = 0;
        while (acc0 + tT + 1 <= p){ tT++; acc0 += tT; }
        int sT = p - acc0;
        Ah = g_qh + (size_t)bh*CT*CNH; Al = g_ql + (size_t)bh*CT*CNH; lda = CNH;
        Bh = Ah; Bl = Al; ldb = CNH;
        m0 = tT*128; n0 = sT*128; Klen = CNH;
    } else if (MODE == M_AMODE){
        Ah = g_sh + (size_t)bh*CT*CT;  Al = g_sl + (size_t)bh*CT*CT;  lda = CT;
        Bh = g_vTh + (size_t)b*CD*CT;  Bl = g_vTl + (size_t)b*CD*CT;  ldb = CT;
        m0 = blockIdx.y*128; n0 = blockIdx.x*128;
        Klen = (blockIdx.y + 1) * 128;                // causal K clamp
    } else if (MODE == M_ENC){
        int z = blockIdx.z;
        Ah = g_yh + (size_t)z*4096;   Al = g_yl + (size_t)z*4096;   lda = CN;
        Bh = g_ench + (size_t)z*4096; Bl = g_encl + (size_t)z*4096; ldb = CN;
        m0 = blockIdx.y*128; n0 = blockIdx.x*128; Klen = 4096;
    } else { // M_RO
        Ah = g_vh; Al = g_vl; lda = CD;
        Bh = g_roh; Bl = g_rol; ldb = CD;
        m0 = blockIdx.y*128; n0 = blockIdx.x*128; Klen = CD;
    }

    float acc[2][8][4];
#pragma unroll
    for (int i = 0; i < 2; i++)
#pragma unroll
        for (int j = 0; j < 8; j++)
#pragma unroll
            for (int q = 0; q < 4; q++) acc[i][j][q] = 0.f;

    const int nch = Klen >> 6;   // KC = 64 halves per chunk

    // ---- async stage issuer: 4 arrays x 128 rows x 8 x 16B, 16 per thread ----
    auto issue = [&](int c){
        uint32_t sbase = smb + (uint32_t)(c & 1) * STAGE_BYTES;
        int kb = c << 6;
        int kc = tid & 7;              // 16B chunk in row
        int rlo = tid >> 3;            // 0..31
#pragma unroll
        for (int it = 0; it < 16; it++){
            int arr = it >> 2;                       // 0=Ah 1=Al 2=Bh 3=Bl
            int r = ((it & 3) << 5) + rlo;           // 0..127
            const __half* gp = (arr == 0) ? Ah : (arr == 1) ? Al : (arr == 2) ? Bh : Bl;
            size_t ld  = (arr < 2) ? lda : ldb;
            int    off = (arr < 2) ? m0  : n0;
            cpa16(sbase + (uint32_t)arr*ARR_BYTES + (uint32_t)r*PITCH + (uint32_t)kc*16,
                  gp + ((size_t)(off + r))*ld + kb + kc*8);
        }
        asm volatile("cp.async.commit_group;" ::: "memory");
    };

    issue(0);
    for (int c = 0; c < nch; c++){
        if (c + 1 < nch){
            issue(c + 1);
            asm volatile("cp.async.wait_group 1;" ::: "memory");
        } else {
            asm volatile("cp.async.wait_group 0;" ::: "memory");
        }
        __syncthreads();

        uint32_t sbase = smb + (uint32_t)(c & 1) * STAGE_BYTES;
        uint32_t sAh = sbase, sAl = sbase + ARR_BYTES;
        uint32_t sBh = sbase + 2*ARR_BYTES, sBl = sbase + 3*ARR_BYTES;

#pragma unroll
        for (int k16 = 0; k16 < 4; k16++){
            uint32_t aH[2][4], aL[2][4];
#pragma unroll
            for (int mi = 0; mi < 2; mi++){
                uint32_t ro = (uint32_t)(wr*32 + mi*16 + (lane & 15))*PITCH
                            + (uint32_t)k16*32 + (uint32_t)(lane >> 4)*16;
                ldm4(aH[mi], sAh + ro);
                ldm4(aL[mi], sAl + ro);
            }
            uint32_t bH[8][2], bL[8][2];
#pragma unroll
            for (int nj2 = 0; nj2 < 4; nj2++){
                uint32_t ro = (uint32_t)(wc*64 + nj2*16 + (lane & 7) + ((lane >> 4) & 1)*8)*PITCH
                            + (uint32_t)k16*32 + (uint32_t)((lane >> 3) & 1)*16;
                uint32_t r4[4];
                ldm4(r4, sBh + ro);
                bH[nj2*2][0] = r4[0]; bH[nj2*2][1] = r4[1];
                bH[nj2*2+1][0] = r4[2]; bH[nj2*2+1][1] = r4[3];
                ldm4(r4, sBl + ro);
                bL[nj2*2][0] = r4[0]; bL[nj2*2][1] = r4[1];
                bL[nj2*2+1][0] = r4[2]; bL[nj2*2+1][1] = r4[3];
            }
#pragma unroll
            for (int mi = 0; mi < 2; mi++)
#pragma unroll
                for (int nj = 0; nj < 8; nj++){
                    mma16816(acc[mi][nj], aH[mi], bH[nj]);
                    mma16816(acc[mi][nj], aH[mi], bL[nj]);
                    mma16816(acc[mi][nj], aL[mi], bH[nj]);
                }
        }
        __syncthreads();
    }

    // ---------------- epilogue: direct from accumulators ----------------
#pragma unroll
    for (int mi = 0; mi < 2; mi++){
#pragma unroll
        for (int nj = 0; nj < 8; nj++){
            int rb = wr*32 + mi*16 + (lane >> 2);
            int cb = wc*64 + nj*8 + ((lane & 3) << 1);
#pragma unroll
            for (int hrow = 0; hrow < 2; hrow++){
                int r = rb + hrow*8;
                float v0 = acc[mi][nj][hrow*2];
                float v1 = acc[mi][nj][hrow*2 + 1];
                int t = m0 + r;

                if (MODE == M_SCORES){
                    int s = n0 + cb;
                    if (s     >= t) v0 = 0.f;
                    if (s + 1 >= t) v1 = 0.f;
                    uint32_t hi, lo;
                    split_pack(v0, v1, hi, lo);
                    size_t o = (size_t)bh*CT*CT + (size_t)t*CT + s;
                    *(uint32_t*)(g_sh + o) = hi;
                    *(uint32_t*)(g_sl + o) = lo;
                } else if (MODE == M_XPROJ){
                    int n = n0 + cb;
                    float x1 = fmaxf(v0, 0.f), x2 = fmaxf(v1, 0.f);
                    size_t xi = (size_t)bh*CT*CNH + (size_t)t*CNH + n;
                    *(float2*)(g_x + xi) = make_float2(x1, x2);
                    int fi = n >> 1;
                    float cs = g_cosT[(size_t)t*FH + fi];
                    float sn = g_sinT[(size_t)t*FH + fi];
                    float q1 = x1*cs - x2*sn;
                    float q2 = x1*sn + x2*cs;
                    uint32_t hi, lo;
                    split_pack(q1, q2, hi, lo);
                    *(uint32_t*)(g_qh + xi) = hi;
                    *(uint32_t*)(g_ql + xi) = lo;
                } else if (MODE == M_YPROJ){
                    int n = n0 + cb;
                    size_t xi = (size_t)bh*CT*CNH + (size_t)t*CNH + n;
                    float2 xv = *(const float2*)(g_x + xi);
                    float y1 = fmaxf(v0, 0.f) * xv.x;
                    float y2 = fmaxf(v1, 0.f) * xv.y;
                    uint32_t hi, lo;
                    split_pack(y1, y2, hi, lo);
                    size_t yi = ((size_t)b*CT + t)*CN + (size_t)h*CNH + n;
                    *(uint32_t*)(g_yh + yi) = hi;
                    *(uint32_t*)(g_yl + yi) = lo;
                } else {
                    float* op; size_t ldo;
                    if (MODE == M_AMODE){ op = g_a + (size_t)bh*CT*CD; ldo = CD; }
                    else if (MODE == M_ENC){ op = g_zp + (size_t)blockIdx.z*CB*CT*CD; ldo = CD; }
                    else { op = out_arg; ldo = CV; }
                    *(float2*)(op + (size_t)t*ldo + n0 + cb) = make_float2(v0, v1);
                }
            }
        }
    }
}

// ---------------- launch ----------------
extern "C" void kernel_launch(void* const* d_in, const int* in_sizes, int n_in,
                              void* d_out, int out_size){
    const int*   idx = (const int*)  d_in[0];
    const float* wte = (const float*)d_in[1];
    const float* enc = (const float*)d_in[2];
    const float* dx  = (const float*)d_in[3];
    const float* dy  = (const float*)d_in[4];
    const float* ro  = (const float*)d_in[5];
    float* out = (float*)d_out;

    static int attr_done = 0;
    if (!attr_done){
        cudaFuncSetAttribute(k_gemm<M_XPROJ>,  cudaFuncAttributeMaxDynamicSharedMemorySize, SMEM_BYTES);
        cudaFuncSetAttribute(k_gemm<M_SCORES>, cudaFuncAttributeMaxDynamicSharedMemorySize, SMEM_BYTES);
        cudaFuncSetAttribute(k_gemm<M_AMODE>,  cudaFuncAttributeMaxDynamicSharedMemorySize, SMEM_BYTES);
        cudaFuncSetAttribute(k_gemm<M_YPROJ>,  cudaFuncAttributeMaxDynamicSharedMemorySize, SMEM_BYTES);
        cudaFuncSetAttribute(k_gemm<M_ENC>,    cudaFuncAttributeMaxDynamicSharedMemorySize, SMEM_BYTES);
        cudaFuncSetAttribute(k_gemm<M_RO>,     cudaFuncAttributeMaxDynamicSharedMemorySize, SMEM_BYTES);
        attr_done = 1;
    }

    k_tables<<<FH, 256>>>();
    k_splitT<<<dim3(CNH/32, CD/32, CH), dim3(32,8)>>>(dx,  0, CD, CNH);
    k_splitT<<<dim3(CNH/32, CD/32, CH), dim3(32,8)>>>(dy,  1, CD, CNH);
    k_splitT<<<dim3(CD/32,  CN/32, 1),  dim3(32,8)>>>(enc, 2, CN, CD);
    k_splitT<<<dim3(CV/32,  CD/32, 1),  dim3(32,8)>>>(ro,  3, CD, CV);
    k_init_v<<<CB*CT, 256>>>(idx, wte);

    for (int l = 0; l < CL; l++){
        k_gemm<M_XPROJ> <<<dim3(CNH/128, CT/128, CB*CH), 256, SMEM_BYTES>>>(nullptr);
        k_gemm<M_SCORES><<<dim3(36,      1,      CB*CH), 256, SMEM_BYTES>>>(nullptr);
        k_gemm<M_AMODE> <<<dim3(CD/128,  CT/128, CB*CH), 256, SMEM_BYTES>>>(nullptr);
        k_lna<<<CB*CH*CT, 256>>>();
        k_gemm<M_YPROJ> <<<dim3(CNH/128, CT/128, CB*CH), 256, SMEM_BYTES>>>(nullptr);
        k_gemm<M_ENC>   <<<dim3(CD/128, (CB*CT)/128, 8), 256, SMEM_BYTES>>>(nullptr);
        k_post<<<CB*CT, 256>>>();
    }
    k_gemm<M_RO><<<dim3(CV/128, (CB*CT)/128, 1), 256, SMEM_BYTES>>>(out);
}

// round 5
// speedup vs baseline: 1.8433x; 1.1928x over previous
#include <cuda_runtime.h>
#include <cuda_fp16.h>
#include <math.h>
#include <stdint.h>

#define CB 2
#define CT 1024
#define CD 256
#define CH 4
#define CNH 8192
#define CN 32768
#define CV 256
#define CL 6
#define FH 4096
#define EPSV 1e-5f

// smem geometry: 4 arrays (Ah, Al, Bh, Bl), 128 rows x 64B data (KC=32), 80B pitch
#define PITCH 80
#define ARR_BYTES (128*PITCH)          // 10240
#define STAGE_BYTES (4*ARR_BYTES)      // 40960
#define SMEM_BYTES (2*STAGE_BYTES)     // 81920  -> 2 CTAs/SM

// ---------------- device scratch ----------------
__device__ __align__(256) float  g_v   [CB*CT*CD];
__device__ __align__(256) __half g_vh  [CB*CT*CD];
__device__ __align__(256) __half g_vl  [CB*CT*CD];
__device__ __align__(256) __half g_vTh [CB*CD*CT];
__device__ __align__(256) __half g_vTl [CB*CD*CT];
__device__ __align__(256) float  g_x   [(size_t)CB*CH*CT*CNH];
__device__ __align__(256) __half g_qh  [(size_t)CB*CH*CT*CNH];
__device__ __align__(256) __half g_ql  [(size_t)CB*CH*CT*CNH];
__device__ __align__(256) __half g_sh  [(size_t)CB*CH*CT*CT];
__device__ __align__(256) __half g_sl  [(size_t)CB*CH*CT*CT];
__device__ __align__(256) float  g_a   [CB*CH*CT*CD];
__device__ __align__(256) __half g_lah [CB*CH*CT*CD];
__device__ __align__(256) __half g_lal [CB*CH*CT*CD];
__device__ __align__(256) __half g_yh  [(size_t)CB*CT*CN];
__device__ __align__(256) __half g_yl  [(size_t)CB*CT*CN];
__device__ __align__(256) float  g_zp  [(size_t)8*CB*CT*CD];
__device__ __align__(256) float  g_cosT[(size_t)CT*FH];
__device__ __align__(256) float  g_sinT[(size_t)CT*FH];
// weights stored TRANSPOSED (K-major for B operand)
__device__ __align__(256) __half g_wxh [(size_t)CH*CD*CNH];
__device__ __align__(256) __half g_wxl [(size_t)CH*CD*CNH];
__device__ __align__(256) __half g_wyh [(size_t)CH*CD*CNH];
__device__ __align__(256) __half g_wyl [(size_t)CH*CD*CNH];
__device__ __align__(256) __half g_ench[(size_t)CN*CD];
__device__ __align__(256) __half g_encl[(size_t)CN*CD];
__device__ __align__(256) __half g_roh [CD*CV];
__device__ __align__(256) __half g_rol [CD*CV];

// ---------------- PTX helpers ----------------
__device__ __forceinline__ uint32_t smem_u32(const void* p){
    uint32_t a;
    asm("{ .reg .u64 t; cvta.to.shared.u64 t, %1; cvt.u32.u64 %0, t; }" : "=r"(a) : "l"(p));
    return a;
}
__device__ __forceinline__ void cpa16(uint32_t s, const void* g){
    asm volatile("cp.async.cg.shared.global [%0], [%1], 16;" :: "r"(s), "l"(g));
}
__device__ __forceinline__ void ldm4(uint32_t* r, uint32_t a){
    asm volatile("ldmatrix.sync.aligned.m8n8.x4.shared.b16 {%0,%1,%2,%3}, [%4];"
        : "=r"(r[0]), "=r"(r[1]), "=r"(r[2]), "=r"(r[3]) : "r"(a));
}
__device__ __forceinline__ void mma16816(float* d, const uint32_t* a, const uint32_t* b){
    asm volatile(
        "mma.sync.aligned.m16n8k16.row.col.f32.f16.f16.f32 "
        "{%0,%1,%2,%3}, {%4,%5,%6,%7}, {%8,%9}, {%0,%1,%2,%3};"
        : "+f"(d[0]), "+f"(d[1]), "+f"(d[2]), "+f"(d[3])
        : "r"(a[0]), "r"(a[1]), "r"(a[2]), "r"(a[3]), "r"(b[0]), "r"(b[1]));
}

// ---------------- small helpers ----------------
__device__ __forceinline__ float blkSum(float v, float* red){
    int lane = threadIdx.x & 31, w = threadIdx.x >> 5;
#pragma unroll
    for (int o = 16; o > 0; o >>= 1) v += __shfl_xor_sync(0xffffffffu, v, o);
    if (lane == 0) red[w] = v;
    __syncthreads();
    float r = 0.f;
#pragma unroll
    for (int i = 0; i < 8; i++) r += red[i];
    __syncthreads();
    return r;
}
__device__ __forceinline__ void split_store(__half* hi, __half* lo, size_t o, float v){
    __half h = __float2half(v);
    hi[o] = h;
    lo[o] = __float2half(v - __half2float(h));
}
__device__ __forceinline__ void split_pack(float v0, float v1, uint32_t& hi, uint32_t& lo){
    __half h0 = __float2half(v0), h1 = __float2half(v1);
    hi = (uint32_t)__half_as_ushort(h0) | ((uint32_t)__half_as_ushort(h1) << 16);
    __half l0 = __float2half(v0 - __half2float(h0));
    __half l1 = __float2half(v1 - __half2float(h1));
    lo = (uint32_t)__half_as_ushort(l0) | ((uint32_t)__half_as_ushort(l1) << 16);
}

// ---------------- init kernels ----------------
__global__ void k_tables(){
    int i = blockIdx.x;
    double ex  = (2.0 * (double)i) / (double)CNH;
    double inv = exp(-ex * 9.210340371976184);
    for (int t = threadIdx.x; t < CT; t += blockDim.x){
        double ang = (double)t * inv;
        double k = rint(ang * 0.15915494309189535);
        float red = (float)(ang - k * 6.283185307179586);
        float s, c;
        sincosf(red, &s, &c);
        g_cosT[(size_t)t*FH + i] = c;
        g_sinT[(size_t)t*FH + i] = s;
    }
}

__global__ void k_splitT(const float* __restrict__ src, int sel, int R, int C){
    __half *hi, *lo;
    if      (sel == 0){ hi = g_wxh;  lo = g_wxl;  }
    else if (sel == 1){ hi = g_wyh;  lo = g_wyl;  }
    else if (sel == 2){ hi = g_ench; lo = g_encl; }
    else              { hi = g_roh;  lo = g_rol;  }
    __shared__ float tile[32][33];
    int h = blockIdx.z;
    const float* s = src + (size_t)h*R*C;
    __half* oh = hi + (size_t)h*R*C;
    __half* ol = lo + (size_t)h*R*C;
    int c0 = blockIdx.x*32, r0 = blockIdx.y*32;
    for (int i = threadIdx.y; i < 32; i += 8)
        tile[i][threadIdx.x] = s[(size_t)(r0+i)*C + c0 + threadIdx.x];
    __syncthreads();
    for (int i = threadIdx.y; i < 32; i += 8){
        float v = tile[threadIdx.x][i];
        __half hh = __float2half(v);
        size_t o = (size_t)(c0+i)*R + r0 + threadIdx.x;
        oh[o] = hh;
        ol[o] = __float2half(v - __half2float(hh));
    }
}

__global__ void k_init_v(const int* __restrict__ idx, const float* __restrict__ wte){
    __shared__ float red[8];
    int bt = blockIdx.x, d = threadIdx.x;
    int b = bt >> 10, t = bt & 1023;
    float x = wte[(size_t)idx[bt]*CD + d];
    float m = blkSum(x, red) * (1.f/CD);
    float c = x - m;
    float var = blkSum(c*c, red) * (1.f/CD);
    float o = c * rsqrtf(var + EPSV);
    size_t oi = (size_t)bt*CD + d;
    g_v[oi] = o;
    split_store(g_vh, g_vl, oi, o);
    split_store(g_vTh, g_vTl, ((size_t)b*CD + d)*CT + t, o);
}

__global__ void k_lna(){
    __shared__ float red[8];
    int row = blockIdx.x, d = threadIdx.x;
    float x = g_a[(size_t)row*CD + d];
    float m = blkSum(x, red) * (1.f/CD);
    float c = x - m;
    float var = blkSum(c*c, red) * (1.f/CD);
    float o = c * rsqrtf(var + EPSV);
    split_store(g_lah, g_lal, (size_t)row*CD + d, o);
}

__global__ void k_post(){
    __shared__ float red[8];
    int row = blockIdx.x, d = threadIdx.x;
    int b = row >> 10, t = row & 1023;
    size_t oi = (size_t)row*CD + d;
    float z = 0.f;
#pragma unroll
    for (int p = 0; p < 8; p++) z += g_zp[(size_t)p*CB*CT*CD + oi];
    float m = blkSum(z, red) * (1.f/CD);
    float c = z - m;
    float var = blkSum(c*c, red) * (1.f/CD);
    float lnz = c * rsqrtf(var + EPSV);
    float u = g_v[oi] + lnz;
    m = blkSum(u, red) * (1.f/CD);
    c = u - m;
    var = blkSum(c*c, red) * (1.f/CD);
    float o = c * rsqrtf(var + EPSV);
    g_v[oi] = o;
    split_store(g_vh, g_vl, oi, o);
    split_store(g_vTh, g_vTl, ((size_t)b*CD + d)*CT + t, o);
}

// ---------------- unified split-fp16 mma.sync GEMM ----------------
#define M_XPROJ  0
#define M_SCORES 1
#define M_AMODE  2
#define M_YPROJ  3
#define M_ENC    4
#define M_RO     5

template<int MODE>
__global__ void __launch_bounds__(256, 2) k_gemm(float* out_arg){
    extern __shared__ __align__(128) char dyn[];
    uint32_t smb = smem_u32(dyn);

    int tid  = threadIdx.x;
    int warp = tid >> 5, lane = tid & 31;
    int wr = warp >> 1, wc = warp & 1;          // warp tile: rows wr*32, cols wc*64

    int bh = blockIdx.z, b = bh >> 2, h = bh & 3;
    const __half *Ah, *Al, *Bh, *Bl;
    size_t lda, ldb;
    int m0, n0, Klen;
    bool shareB = false;

    if (MODE == M_XPROJ){
        Ah = g_vh + (size_t)b*CT*CD;   Al = g_vl + (size_t)b*CT*CD;   lda = CD;
        Bh = g_wxh + (size_t)h*CD*CNH; Bl = g_wxl + (size_t)h*CD*CNH; ldb = CD;
        m0 = blockIdx.y*128; n0 = blockIdx.x*128; Klen = CD;
    } else if (MODE == M_YPROJ){
        Ah = g_lah + (size_t)bh*CT*CD; Al = g_lal + (size_t)bh*CT*CD; lda = CD;
        Bh = g_wyh + (size_t)h*CD*CNH; Bl = g_wyl + (size_t)h*CD*CNH; ldb = CD;
        m0 = blockIdx.y*128; n0 = blockIdx.x*128; Klen = CD;
    } else if (MODE == M_SCORES){
        int p = blockIdx.x, tT = 0, acc0 = 0;
        while (acc0 + tT + 1 <= p){ tT++; acc0 += tT; }
        int sT = p - acc0;
        Ah = g_qh + (size_t)bh*CT*CNH; Al = g_ql + (size_t)bh*CT*CNH; lda = CNH;
        Bh = Ah; Bl = Al; ldb = CNH;
        m0 = tT*128; n0 = sT*128; Klen = CNH;
        shareB = (tT == sT);
    } else if (MODE == M_AMODE){
        Ah = g_sh + (size_t)bh*CT*CT;  Al = g_sl + (size_t)bh*CT*CT;  lda = CT;
        Bh = g_vTh + (size_t)b*CD*CT;  Bl = g_vTl + (size_t)b*CD*CT;  ldb = CT;
        m0 = blockIdx.y*128; n0 = blockIdx.x*128;
        Klen = (blockIdx.y + 1) * 128;                // causal K clamp
    } else if (MODE == M_ENC){
        int z = blockIdx.z;
        Ah = g_yh + (size_t)z*4096;   Al = g_yl + (size_t)z*4096;   lda = CN;
        Bh = g_ench + (size_t)z*4096; Bl = g_encl + (size_t)z*4096; ldb = CN;
        m0 = blockIdx.y*128; n0 = blockIdx.x*128; Klen = 4096;
    } else { // M_RO
        Ah = g_vh; Al = g_vl; lda = CD;
        Bh = g_roh; Bl = g_rol; ldb = CD;
        m0 = blockIdx.y*128; n0 = blockIdx.x*128; Klen = CD;
    }

    float acc[2][8][4];
#pragma unroll
    for (int i = 0; i < 2; i++)
#pragma unroll
        for (int j = 0; j < 8; j++)
#pragma unroll
            for (int q = 0; q < 4; q++) acc[i][j][q] = 0.f;

    const int nch = Klen >> 5;   // KC = 32 halves per chunk

    // ---- async stage issuer: 4 arrays x 128 rows x 4 x 16B, 8 per thread ----
    auto issue = [&](int c){
        uint32_t sbase = smb + (uint32_t)(c & 1) * STAGE_BYTES;
        int kb = c << 5;
        int kc = tid & 3;              // 16B chunk in 64B row
        int rlo = tid >> 2;            // 0..63
        int nArr = shareB ? 2 : 4;
#pragma unroll
        for (int it = 0; it < 8; it++){
            int arr = it >> 1;                       // 0=Ah 1=Al 2=Bh 3=Bl
            if (arr >= nArr) break;
            int r = ((it & 1) << 6) + rlo;           // 0..127
            const __half* gp = (arr == 0) ? Ah : (arr == 1) ? Al : (arr == 2) ? Bh : Bl;
            size_t ld  = (arr < 2) ? lda : ldb;
            int    off = (arr < 2) ? m0  : n0;
            cpa16(sbase + (uint32_t)arr*ARR_BYTES + (uint32_t)r*PITCH + (uint32_t)kc*16,
                  gp + ((size_t)(off + r))*ld + kb + kc*8);
        }
        asm volatile("cp.async.commit_group;" ::: "memory");
    };

    issue(0);
    for (int c = 0; c < nch; c++){
        if (c + 1 < nch){
            issue(c + 1);
            asm volatile("cp.async.wait_group 1;" ::: "memory");
        } else {
            asm volatile("cp.async.wait_group 0;" ::: "memory");
        }
        __syncthreads();

        uint32_t sbase = smb + (uint32_t)(c & 1) * STAGE_BYTES;
        uint32_t sAh = sbase, sAl = sbase + ARR_BYTES;
        uint32_t sBh = shareB ? sAh : (sbase + 2*ARR_BYTES);
        uint32_t sBl = shareB ? sAl : (sbase + 3*ARR_BYTES);

#pragma unroll
        for (int k16 = 0; k16 < 2; k16++){
            uint32_t aH[2][4], aL[2][4];
#pragma unroll
            for (int mi = 0; mi < 2; mi++){
                uint32_t ro = (uint32_t)(wr*32 + mi*16 + (lane & 15))*PITCH
                            + (uint32_t)k16*32 + (uint32_t)(lane >> 4)*16;
                ldm4(aH[mi], sAh + ro);
                ldm4(aL[mi], sAl + ro);
            }
#pragma unroll
            for (int nj2 = 0; nj2 < 4; nj2++){
                uint32_t ro = (uint32_t)(wc*64 + nj2*16 + (lane & 7) + ((lane >> 4) & 1)*8)*PITCH
                            + (uint32_t)k16*32 + (uint32_t)((lane >> 3) & 1)*16;
                uint32_t bh4[4], bl4[4];
                ldm4(bh4, sBh + ro);
                ldm4(bl4, sBl + ro);
#pragma unroll
                for (int mi = 0; mi < 2; mi++){
                    mma16816(acc[mi][nj2*2],     aH[mi], bh4);
                    mma16816(acc[mi][nj2*2],     aH[mi], bl4);
                    mma16816(acc[mi][nj2*2],     aL[mi], bh4);
                    mma16816(acc[mi][nj2*2 + 1], aH[mi], bh4 + 2);
                    mma16816(acc[mi][nj2*2 + 1], aH[mi], bl4 + 2);
                    mma16816(acc[mi][nj2*2 + 1], aL[mi], bh4 + 2);
                }
            }
        }
        __syncthreads();
    }

    // ---------------- epilogue: direct from accumulators ----------------
#pragma unroll
    for (int mi = 0; mi < 2; mi++){
#pragma unroll
        for (int nj = 0; nj < 8; nj++){
            int rb = wr*32 + mi*16 + (lane >> 2);
            int cb = wc*64 + nj*8 + ((lane & 3) << 1);
#pragma unroll
            for (int hrow = 0; hrow < 2; hrow++){
                int r = rb + hrow*8;
                float v0 = acc[mi][nj][hrow*2];
                float v1 = acc[mi][nj][hrow*2 + 1];
                int t = m0 + r;

                if (MODE == M_SCORES){
                    int s = n0 + cb;
                    if (s     >= t) v0 = 0.f;
                    if (s + 1 >= t) v1 = 0.f;
                    uint32_t hi, lo;
                    split_pack(v0, v1, hi, lo);
                    size_t o = (size_t)bh*CT*CT + (size_t)t*CT + s;
                    *(uint32_t*)(g_sh + o) = hi;
                    *(uint32_t*)(g_sl + o) = lo;
                } else if (MODE == M_XPROJ){
                    int n = n0 + cb;
                    float x1 = fmaxf(v0, 0.f), x2 = fmaxf(v1, 0.f);
                    size_t xi = (size_t)bh*CT*CNH + (size_t)t*CNH + n;
                    *(float2*)(g_x + xi) = make_float2(x1, x2);
                    int fi = n >> 1;
                    float cs = g_cosT[(size_t)t*FH + fi];
                    float sn = g_sinT[(size_t)t*FH + fi];
                    float q1 = x1*cs - x2*sn;
                    float q2 = x1*sn + x2*cs;
                    uint32_t hi, lo;
                    split_pack(q1, q2, hi, lo);
                    *(uint32_t*)(g_qh + xi) = hi;
                    *(uint32_t*)(g_ql + xi) = lo;
                } else if (MODE == M_YPROJ){
                    int n = n0 + cb;
                    size_t xi = (size_t)bh*CT*CNH + (size_t)t*CNH + n;
                    float2 xv = *(const float2*)(g_x + xi);
                    float y1 = fmaxf(v0, 0.f) * xv.x;
                    float y2 = fmaxf(v1, 0.f) * xv.y;
                    uint32_t hi, lo;
                    split_pack(y1, y2, hi, lo);
                    size_t yi = ((size_t)b*CT + t)*CN + (size_t)h*CNH + n;
                    *(uint32_t*)(g_yh + yi) = hi;
                    *(uint32_t*)(g_yl + yi) = lo;
                } else {
                    float* op; size_t ldo;
                    if (MODE == M_AMODE){ op = g_a + (size_t)bh*CT*CD; ldo = CD; }
                    else if (MODE == M_ENC){ op = g_zp + (size_t)blockIdx.z*CB*CT*CD; ldo = CD; }
                    else { op = out_arg; ldo = CV; }
                    *(float2*)(op + (size_t)t*ldo + n0 + cb) = make_float2(v0, v1);
                }
            }
        }
    }
}

// ---------------- launch ----------------
extern "C" void kernel_launch(void* const* d_in, const int* in_sizes, int n_in,
                              void* d_out, int out_size){
    const int*   idx = (const int*)  d_in[0];
    const float* wte = (const float*)d_in[1];
    const float* enc = (const float*)d_in[2];
    const float* dx  = (const float*)d_in[3];
    const float* dy  = (const float*)d_in[4];
    const float* ro  = (const float*)d_in[5];
    float* out = (float*)d_out;

    cudaFuncSetAttribute(k_gemm<M_XPROJ>,  cudaFuncAttributeMaxDynamicSharedMemorySize, SMEM_BYTES);
    cudaFuncSetAttribute(k_gemm<M_SCORES>, cudaFuncAttributeMaxDynamicSharedMemorySize, SMEM_BYTES);
    cudaFuncSetAttribute(k_gemm<M_AMODE>,  cudaFuncAttributeMaxDynamicSharedMemorySize, SMEM_BYTES);
    cudaFuncSetAttribute(k_gemm<M_YPROJ>,  cudaFuncAttributeMaxDynamicSharedMemorySize, SMEM_BYTES);
    cudaFuncSetAttribute(k_gemm<M_ENC>,    cudaFuncAttributeMaxDynamicSharedMemorySize, SMEM_BYTES);
    cudaFuncSetAttribute(k_gemm<M_RO>,     cudaFuncAttributeMaxDynamicSharedMemorySize, SMEM_BYTES);

    k_tables<<<FH, 256>>>();
    k_splitT<<<dim3(CNH/32, CD/32, CH), dim3(32,8)>>>(dx,  0, CD, CNH);
    k_splitT<<<dim3(CNH/32, CD/32, CH), dim3(32,8)>>>(dy,  1, CD, CNH);
    k_splitT<<<dim3(CD/32,  CN/32, 1),  dim3(32,8)>>>(enc, 2, CN, CD);
    k_splitT<<<dim3(CV/32,  CD/32, 1),  dim3(32,8)>>>(ro,  3, CD, CV);
    k_init_v<<<CB*CT, 256>>>(idx, wte);

    for (int l = 0; l < CL; l++){
        k_gemm<M_XPROJ> <<<dim3(CNH/128, CT/128, CB*CH), 256, SMEM_BYTES>>>(nullptr);
        k_gemm<M_SCORES><<<dim3(36,      1,      CB*CH), 256, SMEM_BYTES>>>(nullptr);
        k_gemm<M_AMODE> <<<dim3(CD/128,  CT/128, CB*CH), 256, SMEM_BYTES>>>(nullptr);
        k_lna<<<CB*CH*CT, 256>>>();
        k_gemm<M_YPROJ> <<<dim3(CNH/128, CT/128, CB*CH), 256, SMEM_BYTES>>>(nullptr);
        k_gemm<M_ENC>   <<<dim3(CD/128, (CB*CT)/128, 8), 256, SMEM_BYTES>>>(nullptr);
        k_post<<<CB*CT, 256>>>();
    }
    k_gemm<M_RO><<<dim3(CV/128, (CB*CT)/128, 1), 256, SMEM_BYTES>>>(out);
}